// round 1
// baseline (speedup 1.0000x reference)
#include <cuda_runtime.h>
#include <cuda_bf16.h>
#include <cstdint>

// Problem constants
static constexpr int BQ  = 2;
static constexpr int NN  = 2048;
static constexpr int FF  = 64;
static constexpr int HH  = 4;
static constexpr int CC  = 32;
static constexpr int HID = 128;
static constexpr int HIN = 128;   // H*C

// ---------------- device scratch (no cudaMalloc allowed) ----------------
__device__ float g_xp[BQ * NN * HIN];   // per-head features [b,n,h*c]
__device__ float g_es[BQ * NN * HH];    // self scores
__device__ float g_en[BQ * NN * HH];    // neighbor scores
__device__ float g_cu[BQ * NN * HIN];   // conv_u (GAT output + bias)
__device__ float g_t [BQ * NN * HID];   // h' @ R_p

// ---------------- K1: xp = x @ kernel, es/en reductions ----------------
// grid: (B*N/8) blocks, 128 threads. thread t -> column t = h*32 + c.
// Warp w == head w, so the es/en reduction is a pure intra-warp shuffle.
__global__ void k1_project(const float* __restrict__ x,
                           const float* __restrict__ kern,
                           const float* __restrict__ attn_self,
                           const float* __restrict__ attn_nei) {
    __shared__ float xs[8][FF];
    const int row0 = blockIdx.x * 8;
    const int t = threadIdx.x;

    for (int i = t; i < 8 * FF; i += 128) {
        int r = i / FF, f = i % FF;
        xs[r][f] = x[(size_t)(row0 + r) * FF + f];
    }
    __syncthreads();

    const float a_s = attn_self[t];
    const float a_n = attn_nei[t];
    const int h = t >> 5, lane = t & 31;

    float acc[8];
#pragma unroll
    for (int r = 0; r < 8; r++) acc[r] = 0.f;

    for (int f = 0; f < FF; f++) {
        float w = kern[f * HIN + t];
#pragma unroll
        for (int r = 0; r < 8; r++) acc[r] += xs[r][f] * w;
    }

#pragma unroll
    for (int r = 0; r < 8; r++) {
        g_xp[(size_t)(row0 + r) * HIN + t] = acc[r];
        float ps = acc[r] * a_s;
        float pn = acc[r] * a_n;
#pragma unroll
        for (int o = 16; o > 0; o >>= 1) {
            ps += __shfl_down_sync(0xffffffffu, ps, o);
            pn += __shfl_down_sync(0xffffffffu, pn, o);
        }
        if (lane == 0) {
            g_es[(row0 + r) * HH + h] = ps;
            g_en[(row0 + r) * HH + h] = pn;
        }
    }
}

// ---------------- K2: masked softmax attention + sparse aggregation ----------------
// Non-neighbor entries get e - 1e9 -> exp underflows to exactly 0.0f in fp32,
// identical to the dense reference, so neighbor-only computation is bit-faithful.
// grid: B*N blocks, 128 threads. Warp w handles head w.
static constexpr int MAXNBR = 512;   // binomial(2048, 0.01): mean ~21, 512 is >100 sigma

__global__ void k2_attention(const float* __restrict__ a,
                             const float* __restrict__ bias_gat) {
    __shared__ int   nbr[MAXNBR];
    __shared__ float wgt[HH][MAXNBR];
    __shared__ int   cnt;

    const int bi = blockIdx.x;            // b*N + i
    const int b = bi >> 11;
    const int t = threadIdx.x;
    const int h = t >> 5, lane = t & 31;
    const int base = b * NN;

    if (t == 0) cnt = 0;
    __syncthreads();

    const float* arow = a + (size_t)bi * NN;
    for (int j = t; j < NN; j += 128) {
        if (arow[j] != 0.f) {
            int p = atomicAdd(&cnt, 1);
            if (p < MAXNBR) nbr[p] = j;
        }
    }
    __syncthreads();
    const int K = cnt < MAXNBR ? cnt : MAXNBR;

    const float esi = g_es[bi * HH + h];

    // pass 1: per-head max over neighbors
    float m = -1e30f;
    for (int k = lane; k < K; k += 32) {
        float v = esi + g_en[(base + nbr[k]) * HH + h];
        float e = v > 0.f ? v : 0.2f * v;
        m = fmaxf(m, e);
    }
#pragma unroll
    for (int o = 16; o > 0; o >>= 1) m = fmaxf(m, __shfl_xor_sync(0xffffffffu, m, o));

    // pass 2: exp + sum, stash weights
    float s = 0.f;
    for (int k = lane; k < K; k += 32) {
        float v = esi + g_en[(base + nbr[k]) * HH + h];
        float e = v > 0.f ? v : 0.2f * v;
        float w = expf(e - m);
        wgt[h][k] = w;
        s += w;
    }
#pragma unroll
    for (int o = 16; o > 0; o >>= 1) s += __shfl_xor_sync(0xffffffffu, s, o);
    const float inv = 1.f / s;
    __syncwarp();   // wgt[h][*] written/read only within this warp

    // aggregation: out[h, lane] = sum_k w_k * xp[j_k][h*32 + lane]
    float acc = 0.f;
    for (int k = 0; k < K; k++) {
        acc += wgt[h][k] * g_xp[(size_t)(base + nbr[k]) * HIN + t];
    }
    g_cu[(size_t)bi * HIN + t] = acc * inv + bias_gat[t];
}

// ---------------- K3: fused GRU-style gates -> h' ----------------
// grid: (B*N/16) blocks, 128 threads; thread t owns output column t for 16 rows.
__global__ __launch_bounds__(128) void k3_gates(
        const float* __restrict__ h_in,
        const float* __restrict__ bu, const float* __restrict__ br,
        const float* __restrict__ bc,
        const float* __restrict__ Wu, const float* __restrict__ Wr,
        const float* __restrict__ Wc,
        float* __restrict__ hp_out) {
    __shared__ float cu[16][HIN];
    __shared__ float hh[16][HID];
    __shared__ float rh[16][HID];

    const int row0 = blockIdx.x * 16;
    const int t = threadIdx.x;

#pragma unroll
    for (int r = 0; r < 16; r++) {
        cu[r][t] = g_cu[(size_t)(row0 + r) * HIN + t];
        hh[r][t] = h_in[(size_t)(row0 + r) * HID + t];
    }
    __syncthreads();

    float accU[16], accR[16];
#pragma unroll
    for (int r = 0; r < 16; r++) { accU[r] = 0.f; accR[r] = 0.f; }

    for (int i = 0; i < HIN; i++) {
        float wu = Wu[i * HID + t];
        float wr = Wr[i * HID + t];
#pragma unroll
        for (int r = 0; r < 16; r++) {
            float z = cu[r][i];
            accU[r] += z * wu;
            accR[r] += z * wr;
        }
    }
    for (int i = 0; i < HID; i++) {
        float wu = Wu[(HIN + i) * HID + t];
        float wr = Wr[(HIN + i) * HID + t];
#pragma unroll
        for (int r = 0; r < 16; r++) {
            float z = hh[r][i];
            accU[r] += z * wu;
            accR[r] += z * wr;
        }
    }

    float uu[16];
#pragma unroll
    for (int r = 0; r < 16; r++) {
        int n = (row0 + r) & (NN - 1);
        float u  = 1.f / (1.f + expf(-(bu[n] + accU[r])));
        float rr = 1.f / (1.f + expf(-(br[n] + accR[r])));
        uu[r] = u;
        rh[r][t] = rr * hh[r][t];
    }
    __syncthreads();

    float accC[16];
#pragma unroll
    for (int r = 0; r < 16; r++) accC[r] = 0.f;

    for (int i = 0; i < HIN; i++) {
        float wc = Wc[i * HID + t];
#pragma unroll
        for (int r = 0; r < 16; r++) accC[r] += cu[r][i] * wc;
    }
    for (int i = 0; i < HID; i++) {
        float wc = Wc[(HIN + i) * HID + t];
#pragma unroll
        for (int r = 0; r < 16; r++) accC[r] += rh[r][i] * wc;
    }

#pragma unroll
    for (int r = 0; r < 16; r++) {
        int n = (row0 + r) & (NN - 1);
        float c = tanhf(bc[n] + accC[r]);
        float hp = uu[r] * hh[r][t] + (1.f - uu[r]) * c;
        hp_out[(size_t)(row0 + r) * HID + t] = hp;
    }
}

// ---------------- K4: t = h' @ R_p ----------------
__global__ __launch_bounds__(128) void k4_hr(const float* __restrict__ hp,
                                             const float* __restrict__ Rp) {
    __shared__ float hs[16][HID];
    const int row0 = blockIdx.x * 16;
    const int t = threadIdx.x;

#pragma unroll
    for (int r = 0; r < 16; r++) hs[r][t] = hp[(size_t)(row0 + r) * HID + t];
    __syncthreads();

    float acc[16];
#pragma unroll
    for (int r = 0; r < 16; r++) acc[r] = 0.f;

    for (int i = 0; i < HID; i++) {
        float w = Rp[i * HID + t];
#pragma unroll
        for (int r = 0; r < 16; r++) acc[r] += hs[r][i] * w;
    }
#pragma unroll
    for (int r = 0; r < 16; r++) g_t[(size_t)(row0 + r) * HID + t] = acc[r];
}

// ---------------- K5: A[b] = t[b] @ hp[b]^T  (M=N=2048, K=128) ----------------
// 128x128 block tile, BK=16, 8x8 microtile, k-major padded smem.
static constexpr int PAD = 132;

__global__ __launch_bounds__(256, 2) void k5_decode(const float* __restrict__ hp,
                                                    float* __restrict__ A) {
    __shared__ float As[16][PAD];
    __shared__ float Bs[16][PAD];

    const int b    = blockIdx.z;
    const int row0 = blockIdx.y * 128;
    const int col0 = blockIdx.x * 128;
    const float* tm = g_t + (size_t)b * NN * HID;
    const float* hb = hp  + (size_t)b * NN * HID;

    const int tid = threadIdx.x;
    const int tx = tid & 15, ty = tid >> 4;

    float acc[8][8];
#pragma unroll
    for (int u = 0; u < 8; u++)
#pragma unroll
        for (int v = 0; v < 8; v++) acc[u][v] = 0.f;

    const int li = tid >> 2;          // 0..63
    const int lk = (tid & 3) * 4;     // 0,4,8,12

    for (int k0 = 0; k0 < HID; k0 += 16) {
        __syncthreads();
#pragma unroll
        for (int half = 0; half < 2; half++) {
            int i = li + half * 64;
            float4 va = *reinterpret_cast<const float4*>(&tm[(size_t)(row0 + i) * HID + k0 + lk]);
            As[lk + 0][i] = va.x; As[lk + 1][i] = va.y;
            As[lk + 2][i] = va.z; As[lk + 3][i] = va.w;
            float4 vb = *reinterpret_cast<const float4*>(&hb[(size_t)(col0 + i) * HID + k0 + lk]);
            Bs[lk + 0][i] = vb.x; Bs[lk + 1][i] = vb.y;
            Bs[lk + 2][i] = vb.z; Bs[lk + 3][i] = vb.w;
        }
        __syncthreads();

#pragma unroll
        for (int kk = 0; kk < 16; kk++) {
            float a0[8], b0[8];
#pragma unroll
            for (int u = 0; u < 8; u++) a0[u] = As[kk][ty * 8 + u];
#pragma unroll
            for (int v = 0; v < 8; v++) b0[v] = Bs[kk][tx * 8 + v];
#pragma unroll
            for (int u = 0; u < 8; u++)
#pragma unroll
                for (int v = 0; v < 8; v++) acc[u][v] += a0[u] * b0[v];
        }
    }

    float* Ab = A + (size_t)b * NN * NN;
#pragma unroll
    for (int u = 0; u < 8; u++) {
        int rr = row0 + ty * 8 + u;
#pragma unroll
        for (int v = 0; v < 8; v += 4) {
            float4 w = make_float4(acc[u][v], acc[u][v + 1], acc[u][v + 2], acc[u][v + 3]);
            *reinterpret_cast<float4*>(&Ab[(size_t)rr * NN + col0 + tx * 8 + v]) = w;
        }
    }
}

// ---------------- launch ----------------
extern "C" void kernel_launch(void* const* d_in, const int* in_sizes, int n_in,
                              void* d_out, int out_size) {
    (void)in_sizes; (void)n_in; (void)out_size;
    const float* x    = (const float*)d_in[0];
    const float* a    = (const float*)d_in[1];
    const float* h    = (const float*)d_in[2];
    const float* kern = (const float*)d_in[3];
    const float* asf  = (const float*)d_in[4];
    const float* anb  = (const float*)d_in[5];
    const float* bias = (const float*)d_in[6];
    const float* bu   = (const float*)d_in[7];
    const float* br   = (const float*)d_in[8];
    const float* bc   = (const float*)d_in[9];
    const float* Wu   = (const float*)d_in[10];
    const float* Wr   = (const float*)d_in[11];
    const float* Wc   = (const float*)d_in[12];
    const float* Rp   = (const float*)d_in[13];

    float* A  = (float*)d_out;                       // [B,N,N]
    float* hp = A + (size_t)BQ * NN * NN;            // [B,N,HID]

    k1_project <<< (BQ * NN) / 8, 128 >>> (x, kern, asf, anb);
    k2_attention <<< BQ * NN, 128 >>> (a, bias);
    k3_gates <<< (BQ * NN) / 16, 128 >>> (h, bu, br, bc, Wu, Wr, Wc, hp);
    k4_hr <<< (BQ * NN) / 16, 128 >>> (hp, Rp);
    dim3 g5(NN / 128, NN / 128, BQ);
    k5_decode <<< g5, 256 >>> (hp, A);
}

// round 2
// speedup vs baseline: 1.2149x; 1.2149x over previous
#include <cuda_runtime.h>
#include <cuda_bf16.h>
#include <cstdint>

// Problem constants
static constexpr int BQ  = 2;
static constexpr int NN  = 2048;
static constexpr int FF  = 64;
static constexpr int HH  = 4;
static constexpr int HID = 128;
static constexpr int HIN = 128;   // H*C

// ---------------- device scratch (no cudaMalloc allowed) ----------------
__device__ float g_xp[BQ * NN * HIN];   // per-head features [b,n,h*c]
__device__ float g_es[BQ * NN * HH];    // self scores
__device__ float g_en[BQ * NN * HH];    // neighbor scores
__device__ float g_cu[BQ * NN * HIN];   // conv_u (GAT output + bias)
__device__ float g_t [BQ * NN * HID];   // h' @ R_p

// ---------------- K1: xp = x @ kernel, es/en reductions ----------------
__global__ void k1_project(const float* __restrict__ x,
                           const float* __restrict__ kern,
                           const float* __restrict__ attn_self,
                           const float* __restrict__ attn_nei) {
    __shared__ float xs[8][FF];
    const int row0 = blockIdx.x * 8;
    const int t = threadIdx.x;

    for (int i = t; i < 8 * FF; i += 128) {
        int r = i / FF, f = i % FF;
        xs[r][f] = x[(size_t)(row0 + r) * FF + f];
    }
    __syncthreads();

    const float a_s = attn_self[t];
    const float a_n = attn_nei[t];
    const int h = t >> 5, lane = t & 31;

    float acc[8];
#pragma unroll
    for (int r = 0; r < 8; r++) acc[r] = 0.f;

    for (int f = 0; f < FF; f++) {
        float w = kern[f * HIN + t];
#pragma unroll
        for (int r = 0; r < 8; r++) acc[r] += xs[r][f] * w;
    }

#pragma unroll
    for (int r = 0; r < 8; r++) {
        g_xp[(size_t)(row0 + r) * HIN + t] = acc[r];
        float ps = acc[r] * a_s;
        float pn = acc[r] * a_n;
#pragma unroll
        for (int o = 16; o > 0; o >>= 1) {
            ps += __shfl_down_sync(0xffffffffu, ps, o);
            pn += __shfl_down_sync(0xffffffffu, pn, o);
        }
        if (lane == 0) {
            g_es[(row0 + r) * HH + h] = ps;
            g_en[(row0 + r) * HH + h] = pn;
        }
    }
}

// ---------------- K2: masked softmax attention + sparse aggregation ----------------
// Masked entries underflow to exactly 0.0f in fp32 (exp(-1e9-ish)), identical to
// the dense reference, so neighbor-only computation is faithful.
static constexpr int MAXNBR = 512;

__global__ void k2_attention(const float* __restrict__ a,
                             const float* __restrict__ bias_gat) {
    __shared__ int   nbr[MAXNBR];
    __shared__ float wgt[HH][MAXNBR];
    __shared__ int   cnt;

    const int bi = blockIdx.x;            // b*N + i
    const int b = bi >> 11;
    const int t = threadIdx.x;
    const int h = t >> 5, lane = t & 31;
    const int base = b * NN;

    if (t == 0) cnt = 0;
    __syncthreads();

    // vectorized adjacency-row scan
    const float4* arow4 = reinterpret_cast<const float4*>(a + (size_t)bi * NN);
    for (int j4 = t; j4 < NN / 4; j4 += 128) {
        float4 v = arow4[j4];
        if (v.x != 0.f) { int p = atomicAdd(&cnt, 1); if (p < MAXNBR) nbr[p] = j4 * 4 + 0; }
        if (v.y != 0.f) { int p = atomicAdd(&cnt, 1); if (p < MAXNBR) nbr[p] = j4 * 4 + 1; }
        if (v.z != 0.f) { int p = atomicAdd(&cnt, 1); if (p < MAXNBR) nbr[p] = j4 * 4 + 2; }
        if (v.w != 0.f) { int p = atomicAdd(&cnt, 1); if (p < MAXNBR) nbr[p] = j4 * 4 + 3; }
    }
    __syncthreads();
    const int K = cnt < MAXNBR ? cnt : MAXNBR;

    const float esi = g_es[bi * HH + h];

    // pass 1: per-head max over neighbors
    float m = -1e30f;
    for (int k = lane; k < K; k += 32) {
        float v = esi + g_en[(base + nbr[k]) * HH + h];
        float e = v > 0.f ? v : 0.2f * v;
        m = fmaxf(m, e);
    }
#pragma unroll
    for (int o = 16; o > 0; o >>= 1) m = fmaxf(m, __shfl_xor_sync(0xffffffffu, m, o));

    // pass 2: exp + sum
    float s = 0.f;
    for (int k = lane; k < K; k += 32) {
        float v = esi + g_en[(base + nbr[k]) * HH + h];
        float e = v > 0.f ? v : 0.2f * v;
        float w = expf(e - m);
        wgt[h][k] = w;
        s += w;
    }
#pragma unroll
    for (int o = 16; o > 0; o >>= 1) s += __shfl_xor_sync(0xffffffffu, s, o);
    const float inv = 1.f / s;
    __syncwarp();

    float acc = 0.f;
    for (int k = 0; k < K; k++) {
        acc += wgt[h][k] * g_xp[(size_t)(base + nbr[k]) * HIN + t];
    }
    g_cu[(size_t)bi * HIN + t] = acc * inv + bias_gat[t];
}

// ---------------- K3: fused GRU gates + h'@R_p ----------------
// 256 threads: col = t & 127, half = t >> 7; each thread owns 8 of 16 rows.
__global__ __launch_bounds__(256) void k3_gates(
        const float* __restrict__ h_in,
        const float* __restrict__ bu, const float* __restrict__ br,
        const float* __restrict__ bc,
        const float* __restrict__ Wu, const float* __restrict__ Wr,
        const float* __restrict__ Wc, const float* __restrict__ Rp,
        float* __restrict__ hp_out) {
    __shared__ float cu[16][HIN];
    __shared__ float hh[16][HID];
    __shared__ float rh[16][HID];

    const int row0 = blockIdx.x * 16;
    const int t = threadIdx.x;
    const int col = t & 127;
    const int r0 = (t >> 7) * 8;

    float hval[8];
#pragma unroll
    for (int r = 0; r < 8; r++) {
        cu[r0 + r][col] = g_cu[(size_t)(row0 + r0 + r) * HIN + col];
        hval[r] = h_in[(size_t)(row0 + r0 + r) * HID + col];
        hh[r0 + r][col] = hval[r];
    }
    __syncthreads();

    float accU[8], accR[8];
#pragma unroll
    for (int r = 0; r < 8; r++) { accU[r] = 0.f; accR[r] = 0.f; }

    for (int i = 0; i < HIN; i++) {
        float wu = Wu[i * HID + col];
        float wr = Wr[i * HID + col];
#pragma unroll
        for (int r = 0; r < 8; r++) {
            float z = cu[r0 + r][i];
            accU[r] += z * wu;
            accR[r] += z * wr;
        }
    }
    for (int i = 0; i < HID; i++) {
        float wu = Wu[(HIN + i) * HID + col];
        float wr = Wr[(HIN + i) * HID + col];
#pragma unroll
        for (int r = 0; r < 8; r++) {
            float z = hh[r0 + r][i];
            accU[r] += z * wu;
            accR[r] += z * wr;
        }
    }

    float uu[8];
#pragma unroll
    for (int r = 0; r < 8; r++) {
        int n = (row0 + r0 + r) & (NN - 1);
        float u  = 1.f / (1.f + expf(-(bu[n] + accU[r])));
        float rr = 1.f / (1.f + expf(-(br[n] + accR[r])));
        uu[r] = u;
        rh[r0 + r][col] = rr * hval[r];
    }
    __syncthreads();

    float accC[8];
#pragma unroll
    for (int r = 0; r < 8; r++) accC[r] = 0.f;

    for (int i = 0; i < HIN; i++) {
        float wc = Wc[i * HID + col];
#pragma unroll
        for (int r = 0; r < 8; r++) accC[r] += cu[r0 + r][i] * wc;
    }
    for (int i = 0; i < HID; i++) {
        float wc = Wc[(HIN + i) * HID + col];
#pragma unroll
        for (int r = 0; r < 8; r++) accC[r] += rh[r0 + r][i] * wc;
    }

    float hpv[8];
#pragma unroll
    for (int r = 0; r < 8; r++) {
        int n = (row0 + r0 + r) & (NN - 1);
        float c = tanhf(bc[n] + accC[r]);
        hpv[r] = uu[r] * hval[r] + (1.f - uu[r]) * c;
        hp_out[(size_t)(row0 + r0 + r) * HID + col] = hpv[r];
    }
    __syncthreads();                       // rh reads done, safe to overwrite
#pragma unroll
    for (int r = 0; r < 8; r++) rh[r0 + r][col] = hpv[r];
    __syncthreads();

    // t = hp @ Rp
    float accT[8];
#pragma unroll
    for (int r = 0; r < 8; r++) accT[r] = 0.f;
    for (int i = 0; i < HID; i++) {
        float w = Rp[i * HID + col];
#pragma unroll
        for (int r = 0; r < 8; r++) accT[r] += rh[r0 + r][i] * w;
    }
#pragma unroll
    for (int r = 0; r < 8; r++)
        g_t[(size_t)(row0 + r0 + r) * HID + col] = accT[r];
}

// ---------------- K5: A[b] = t[b] @ hp[b]^T  (M=N=2048, K=128) ----------------
// 128x128 tile, BK=16, 8x8 microtile, register-prefetch pipelined smem.
static constexpr int PAD = 132;

__global__ __launch_bounds__(256, 2) void k5_decode(const float* __restrict__ hp,
                                                    float* __restrict__ A) {
    __shared__ float As[16][PAD];
    __shared__ float Bs[16][PAD];

    const int b    = blockIdx.z;
    const int row0 = blockIdx.y * 128;
    const int col0 = blockIdx.x * 128;
    const float* tm = g_t + (size_t)b * NN * HID;
    const float* hb = hp  + (size_t)b * NN * HID;

    const int tid = threadIdx.x;
    const int tx = tid & 15, ty = tid >> 4;

    float acc[8][8];
#pragma unroll
    for (int u = 0; u < 8; u++)
#pragma unroll
        for (int v = 0; v < 8; v++) acc[u][v] = 0.f;

    const int li = tid >> 2;          // 0..63
    const int lk = (tid & 3) * 4;     // 0,4,8,12

    // prologue: load K-tile 0 into registers
    float4 va0, va1, vb0, vb1;
    va0 = *reinterpret_cast<const float4*>(&tm[(size_t)(row0 + li)      * HID + lk]);
    va1 = *reinterpret_cast<const float4*>(&tm[(size_t)(row0 + li + 64) * HID + lk]);
    vb0 = *reinterpret_cast<const float4*>(&hb[(size_t)(col0 + li)      * HID + lk]);
    vb1 = *reinterpret_cast<const float4*>(&hb[(size_t)(col0 + li + 64) * HID + lk]);

    for (int k0 = 0; k0 < HID; k0 += 16) {
        // stage regs -> smem (transpose to k-major)
        As[lk + 0][li] = va0.x; As[lk + 1][li] = va0.y;
        As[lk + 2][li] = va0.z; As[lk + 3][li] = va0.w;
        As[lk + 0][li + 64] = va1.x; As[lk + 1][li + 64] = va1.y;
        As[lk + 2][li + 64] = va1.z; As[lk + 3][li + 64] = va1.w;
        Bs[lk + 0][li] = vb0.x; Bs[lk + 1][li] = vb0.y;
        Bs[lk + 2][li] = vb0.z; Bs[lk + 3][li] = vb0.w;
        Bs[lk + 0][li + 64] = vb1.x; Bs[lk + 1][li + 64] = vb1.y;
        Bs[lk + 2][li + 64] = vb1.z; Bs[lk + 3][li + 64] = vb1.w;
        __syncthreads();

        // issue next tile's global loads (latency overlaps compute below)
        if (k0 + 16 < HID) {
            int kn = k0 + 16 + lk;
            va0 = *reinterpret_cast<const float4*>(&tm[(size_t)(row0 + li)      * HID + kn]);
            va1 = *reinterpret_cast<const float4*>(&tm[(size_t)(row0 + li + 64) * HID + kn]);
            vb0 = *reinterpret_cast<const float4*>(&hb[(size_t)(col0 + li)      * HID + kn]);
            vb1 = *reinterpret_cast<const float4*>(&hb[(size_t)(col0 + li + 64) * HID + kn]);
        }

#pragma unroll
        for (int kk = 0; kk < 16; kk++) {
            float a0[8], b0[8];
#pragma unroll
            for (int u = 0; u < 8; u++) a0[u] = As[kk][ty * 8 + u];
#pragma unroll
            for (int v = 0; v < 8; v++) b0[v] = Bs[kk][tx * 8 + v];
#pragma unroll
            for (int u = 0; u < 8; u++)
#pragma unroll
                for (int v = 0; v < 8; v++) acc[u][v] += a0[u] * b0[v];
        }
        __syncthreads();
    }

    float* Ab = A + (size_t)b * NN * NN;
#pragma unroll
    for (int u = 0; u < 8; u++) {
        int rr = row0 + ty * 8 + u;
#pragma unroll
        for (int v = 0; v < 8; v += 4) {
            float4 w = make_float4(acc[u][v], acc[u][v + 1], acc[u][v + 2], acc[u][v + 3]);
            *reinterpret_cast<float4*>(&Ab[(size_t)rr * NN + col0 + tx * 8 + v]) = w;
        }
    }
}

// ---------------- launch ----------------
extern "C" void kernel_launch(void* const* d_in, const int* in_sizes, int n_in,
                              void* d_out, int out_size) {
    (void)in_sizes; (void)n_in; (void)out_size;
    const float* x    = (const float*)d_in[0];
    const float* a    = (const float*)d_in[1];
    const float* h    = (const float*)d_in[2];
    const float* kern = (const float*)d_in[3];
    const float* asf  = (const float*)d_in[4];
    const float* anb  = (const float*)d_in[5];
    const float* bias = (const float*)d_in[6];
    const float* bu   = (const float*)d_in[7];
    const float* br   = (const float*)d_in[8];
    const float* bc   = (const float*)d_in[9];
    const float* Wu   = (const float*)d_in[10];
    const float* Wr   = (const float*)d_in[11];
    const float* Wc   = (const float*)d_in[12];
    const float* Rp   = (const float*)d_in[13];

    float* A  = (float*)d_out;                       // [B,N,N]
    float* hp = A + (size_t)BQ * NN * NN;            // [B,N,HID]

    k1_project <<< (BQ * NN) / 8, 128 >>> (x, kern, asf, anb);
    k2_attention <<< BQ * NN, 128 >>> (a, bias);
    k3_gates <<< (BQ * NN) / 16, 256 >>> (h, bu, br, bc, Wu, Wr, Wc, Rp, hp);
    dim3 g5(NN / 128, NN / 128, BQ);
    k5_decode <<< g5, 256 >>> (hp, A);
}